// round 10
// baseline (speedup 1.0000x reference)
#include <cuda_runtime.h>
#include <math.h>

#define HID  2048
#define NH   16
#define NKV  8
#define HD   128
#define B_C  2
#define S_C  2048
#define BS_C (B_C * S_C)

// ---------------- scratch (device globals; no allocation allowed) ----------
__device__ float g_q[(size_t)BS_C * NH * HD];     // (B*S, 2048) pre/post-RoPE Q
__device__ float g_k[(size_t)BS_C * NKV * HD];    // (B*S, 1024)
__device__ float g_v[(size_t)BS_C * NKV * HD];    // (B*S, 1024)
__device__ float g_comb[(size_t)BS_C * HID];      // combined (B,S,2048)

__device__ __forceinline__ float elu1(float x) { return x > 0.f ? x + 1.f : expf(x); }

// ---------------- 128x128x8 SGEMM, row-major A(MxK) * B(KxN) -> C(MxN) -----
__global__ __launch_bounds__(256, 2)
void sgemm128(const float* __restrict__ A, const float* __restrict__ Bm,
              float* __restrict__ C, int M, int N, int K) {
    __shared__ float As[8][128];   // [k][m] transposed
    __shared__ float Bs[8][128];   // [k][n]
    const int tid  = threadIdx.x;
    const int tx   = tid & 15, ty = tid >> 4;
    const int row0 = blockIdx.y * 128, col0 = blockIdx.x * 128;
    const int a_row = tid >> 1,  a_col = (tid & 1) << 2;
    const int b_row = tid >> 5,  b_col = (tid & 31) << 2;
    const float* Aptr = A + (size_t)(row0 + a_row) * K + a_col;
    const float* Bptr = Bm + (size_t)b_row * N + col0 + b_col;

    float acc[8][8];
#pragma unroll
    for (int i = 0; i < 8; i++)
#pragma unroll
        for (int j = 0; j < 8; j++) acc[i][j] = 0.f;

    for (int k0 = 0; k0 < K; k0 += 8) {
        float4 av = *(const float4*)(Aptr + k0);
        As[a_col + 0][a_row] = av.x;
        As[a_col + 1][a_row] = av.y;
        As[a_col + 2][a_row] = av.z;
        As[a_col + 3][a_row] = av.w;
        *(float4*)&Bs[b_row][b_col] = *(const float4*)(Bptr + (size_t)k0 * N);
        __syncthreads();
#pragma unroll
        for (int k = 0; k < 8; k++) {
            float a[8], b[8];
            *(float4*)&a[0] = *(const float4*)&As[k][ty * 8];
            *(float4*)&a[4] = *(const float4*)&As[k][ty * 8 + 4];
            *(float4*)&b[0] = *(const float4*)&Bs[k][tx * 8];
            *(float4*)&b[4] = *(const float4*)&Bs[k][tx * 8 + 4];
#pragma unroll
            for (int i = 0; i < 8; i++)
#pragma unroll
                for (int j = 0; j < 8; j++)
                    acc[i][j] += a[i] * b[j];
        }
        __syncthreads();
    }
#pragma unroll
    for (int i = 0; i < 8; i++) {
        float* cp = C + (size_t)(row0 + ty * 8 + i) * N + col0 + tx * 8;
        *(float4*)cp       = make_float4(acc[i][0], acc[i][1], acc[i][2], acc[i][3]);
        *(float4*)(cp + 4) = make_float4(acc[i][4], acc[i][5], acc[i][6], acc[i][7]);
    }
}

// ---------------- init: copy memory_in / norm_in into output slots ---------
__global__ void init_out_kernel(const float* __restrict__ mem_in,
                                const float* __restrict__ norm_in,
                                float* __restrict__ out_mem,
                                float* __restrict__ out_norm,
                                int nmem, int nnorm) {
    int idx = blockIdx.x * blockDim.x + threadIdx.x;
    if (idx < nmem)  out_mem[idx]  = mem_in[idx];
    if (idx < nnorm) out_norm[idx] = norm_in[idx];
}

// ---------------- updated_memory += sigma_k^T @ v ; updated_norm += sum ----
// grid (B*NKV, SPLITS), block 256. Atomic-accumulate into d_out.
__global__ __launch_bounds__(256)
void mem_update_kernel(const float* __restrict__ kbuf, const float* __restrict__ vbuf,
                       float* __restrict__ out_mem, float* __restrict__ out_norm,
                       int B, int S) {
    __shared__ float As[8][128];  // sigma_k [s][d]
    __shared__ float Bs[8][128];  // v       [s][e]
    const int tid = threadIdx.x;
    const int bkv = blockIdx.x;
    const int b = bkv >> 3, kv = bkv & 7;
    const int schunk = S / gridDim.y;
    const int s0 = blockIdx.y * schunk;
    const int tx = tid & 15, ty = tid >> 4;
    const int lr = tid >> 5,  lc = (tid & 31) << 2;

    float acc[8][8];
#pragma unroll
    for (int i = 0; i < 8; i++)
#pragma unroll
        for (int j = 0; j < 8; j++) acc[i][j] = 0.f;
    float nacc = 0.f;

    for (int ks = s0; ks < s0 + schunk; ks += 8) {
        size_t rowb = (size_t)(b * S + ks + lr);
        float4 kk = *(const float4*)(kbuf + rowb * (NKV * HD) + kv * HD + lc);
        As[lr][lc + 0] = elu1(kk.x);
        As[lr][lc + 1] = elu1(kk.y);
        As[lr][lc + 2] = elu1(kk.z);
        As[lr][lc + 3] = elu1(kk.w);
        *(float4*)&Bs[lr][lc] = *(const float4*)(vbuf + rowb * (NKV * HD) + kv * HD + lc);
        __syncthreads();
        if (tid < 128) {
#pragma unroll
            for (int r = 0; r < 8; r++) nacc += As[r][tid];
        }
#pragma unroll
        for (int k = 0; k < 8; k++) {
            float a[8], bb[8];
            *(float4*)&a[0]  = *(const float4*)&As[k][ty * 8];
            *(float4*)&a[4]  = *(const float4*)&As[k][ty * 8 + 4];
            *(float4*)&bb[0] = *(const float4*)&Bs[k][tx * 8];
            *(float4*)&bb[4] = *(const float4*)&Bs[k][tx * 8 + 4];
#pragma unroll
            for (int i = 0; i < 8; i++)
#pragma unroll
                for (int j = 0; j < 8; j++)
                    acc[i][j] += a[i] * bb[j];
        }
        __syncthreads();
    }
    float* mp = out_mem + (size_t)bkv * HD * HD;
#pragma unroll
    for (int i = 0; i < 8; i++)
#pragma unroll
        for (int j = 0; j < 8; j++)
            atomicAdd(mp + (ty * 8 + i) * HD + tx * 8 + j, acc[i][j]);
    if (tid < 128) atomicAdd(out_norm + bkv * HD + tid, nacc);
}

// ---------------- memory_output = g * (sigma_q @ M) / (sigma_q . norm) -----
// grid (B*NH, S/128), block 256. Writes combined buffer (g*mem part).
__global__ __launch_bounds__(256)
void mem_output_kernel(const float* __restrict__ qbuf,
                       const float* __restrict__ mem_in,
                       const float* __restrict__ norm_in,
                       const float* __restrict__ gate,
                       float* __restrict__ comb, int B, int S) {
    __shared__ float As[8][128];  // sigma_q transposed [d][s]
    __shared__ float Bs[8][128];  // mem [d][e]
    __shared__ float Ns[8];       // norm chunk
    const int tid = threadIdx.x;
    const int bh = blockIdx.x;
    const int b = bh >> 4, h = bh & 15;
    const int kv = h & 7;                 // jnp.tile: head h -> kv = h % 8
    const int s0 = blockIdx.y * 128;
    const int tx = tid & 15, ty = tid >> 4;
    const int a_row = tid >> 1, a_col = (tid & 1) << 2;
    const int lr = tid >> 5,    lc = (tid & 31) << 2;

    const float* memp  = mem_in  + (size_t)(b * NKV + kv) * HD * HD;
    const float* normp = norm_in + (size_t)(b * NKV + kv) * HD;

    float acc[8][8];
#pragma unroll
    for (int i = 0; i < 8; i++)
#pragma unroll
        for (int j = 0; j < 8; j++) acc[i][j] = 0.f;
    float nacc[8] = {0.f, 0.f, 0.f, 0.f, 0.f, 0.f, 0.f, 0.f};

    for (int d0 = 0; d0 < HD; d0 += 8) {
        float4 qv = *(const float4*)(qbuf + ((size_t)(b * S + s0 + a_row)) * (NH * HD)
                                     + h * HD + d0 + a_col);
        As[a_col + 0][a_row] = elu1(qv.x);
        As[a_col + 1][a_row] = elu1(qv.y);
        As[a_col + 2][a_row] = elu1(qv.z);
        As[a_col + 3][a_row] = elu1(qv.w);
        *(float4*)&Bs[lr][lc] = *(const float4*)(memp + (d0 + lr) * HD + lc);
        if (tid < 8) Ns[tid] = normp[d0 + tid];
        __syncthreads();
#pragma unroll
        for (int k = 0; k < 8; k++) {
            float a[8], bb[8];
            *(float4*)&a[0]  = *(const float4*)&As[k][ty * 8];
            *(float4*)&a[4]  = *(const float4*)&As[k][ty * 8 + 4];
            *(float4*)&bb[0] = *(const float4*)&Bs[k][tx * 8];
            *(float4*)&bb[4] = *(const float4*)&Bs[k][tx * 8 + 4];
            float nk = Ns[k];
#pragma unroll
            for (int i = 0; i < 8; i++) {
                nacc[i] += a[i] * nk;
#pragma unroll
                for (int j = 0; j < 8; j++)
                    acc[i][j] += a[i] * bb[j];
            }
        }
        __syncthreads();
    }
    float g = 1.f / (1.f + expf(-gate[h]));
#pragma unroll
    for (int i = 0; i < 8; i++) {
        float gi = g / nacc[i];
        float* cp = comb + ((size_t)(b * S + s0 + ty * 8 + i)) * HID + h * HD + tx * 8;
        *(float4*)cp       = make_float4(acc[i][0]*gi, acc[i][1]*gi, acc[i][2]*gi, acc[i][3]*gi);
        *(float4*)(cp + 4) = make_float4(acc[i][4]*gi, acc[i][5]*gi, acc[i][6]*gi, acc[i][7]*gi);
    }
}

// ---------------- RoPE in place -------------------------------------------
__global__ void rope_kernel(float* __restrict__ buf, const int* __restrict__ posids,
                            int heads, int S, long total) {
    long idx = (long)blockIdx.x * blockDim.x + threadIdx.x;
    if (idx >= total) return;
    int dh = (int)(idx & 63);
    long t = idx >> 6;
    int h = (int)(t % heads);
    long bs = t / heads;
    int s = (int)(bs % S);
    float pos = (float)posids[s];
    float inv = powf(10000.f, -((float)(2 * dh)) * (1.f / 128.f));
    float ang = pos * inv;
    float sn, c;
    sincosf(ang, &sn, &c);
    float* p = buf + bs * (size_t)heads * HD + (size_t)h * HD;
    float x1 = p[dh], x2 = p[dh + 64];
    p[dh]      = x1 * c - x2 * sn;
    p[dh + 64] = x2 * c + x1 * sn;
}

// ---------------- causal flash attention, adds (1-g)*attn into comb --------
// grid (S/64, B*NH), block 256, dynamic smem.
#define FBM 64
#define FBN 64
#define QK_STRIDE 68   // padded d-major stride (16B-aligned, kills conflicts)

__global__ void flash_kernel(const float* __restrict__ qbuf,
                             const float* __restrict__ kbuf,
                             const float* __restrict__ vbuf,
                             const float* __restrict__ gate,
                             float* __restrict__ comb, int B, int S) {
    extern __shared__ float sm[];
    float* Qs = sm;                          // [128][QK_STRIDE] d-major
    float* Ks = Qs + 128 * QK_STRIDE;        // [128][QK_STRIDE] d-major
    float* Vs = Ks + 128 * QK_STRIDE;        // [64][128] row-major
    float* Ps = Vs + FBN * 128;              // [64][64] row-major

    const int tid = threadIdx.x;
    const int bh = blockIdx.y;
    const int b = bh >> 4, h = bh & 15;
    const int kvh = h >> 1;                  // jnp.repeat: head h -> kv = h / 2
    const int qt = (gridDim.x - 1) - blockIdx.x;   // heavy tiles launch first
    const int q0 = qt * FBM;
    const float scale = 0.08838834764831845f;      // 1/sqrt(128)

    // load Q tile (scaled), transpose to d-major
    {
        const float* qp = qbuf + ((size_t)(b * S + q0)) * (NH * HD) + h * HD;
        for (int t = tid; t < FBM * 32; t += 256) {
            int r = t >> 5; int c4 = (t & 31) << 2;
            float4 v = *(const float4*)(qp + (size_t)r * (NH * HD) + c4);
            Qs[(c4 + 0) * QK_STRIDE + r] = v.x * scale;
            Qs[(c4 + 1) * QK_STRIDE + r] = v.y * scale;
            Qs[(c4 + 2) * QK_STRIDE + r] = v.z * scale;
            Qs[(c4 + 3) * QK_STRIDE + r] = v.w * scale;
        }
    }
    const int tx = tid & 15, ty = tid >> 4;
    const int r0 = ty * 4;       // rows (score & O)
    const int cs0 = tx * 4;      // score cols
    const int co0 = tx * 8;      // O cols

    float o[4][8];
#pragma unroll
    for (int i = 0; i < 4; i++)
#pragma unroll
        for (int j = 0; j < 8; j++) o[i][j] = 0.f;
    float m_i[4] = {-1e30f, -1e30f, -1e30f, -1e30f};
    float l_i[4] = {0.f, 0.f, 0.f, 0.f};

    const int nkt = qt + 1;
    for (int kt = 0; kt < nkt; kt++) {
        const int k0 = kt * FBN;
        __syncthreads();   // protect K/V/P reuse (and Qs on first iter)
        const float* kp = kbuf + ((size_t)(b * S + k0)) * (NKV * HD) + kvh * HD;
        const float* vp = vbuf + ((size_t)(b * S + k0)) * (NKV * HD) + kvh * HD;
        for (int t = tid; t < FBN * 32; t += 256) {
            int r = t >> 5; int c4 = (t & 31) << 2;
            float4 kk = *(const float4*)(kp + (size_t)r * (NKV * HD) + c4);
            Ks[(c4 + 0) * QK_STRIDE + r] = kk.x;
            Ks[(c4 + 1) * QK_STRIDE + r] = kk.y;
            Ks[(c4 + 2) * QK_STRIDE + r] = kk.z;
            Ks[(c4 + 3) * QK_STRIDE + r] = kk.w;
            *(float4*)(Vs + r * 128 + c4) = *(const float4*)(vp + (size_t)r * (NKV * HD) + c4);
        }
        __syncthreads();

        // scores: S[64][64] = Q K^T (scaled)
        float s4[4][4];
#pragma unroll
        for (int i = 0; i < 4; i++)
#pragma unroll
            for (int j = 0; j < 4; j++) s4[i][j] = 0.f;
#pragma unroll 4
        for (int d = 0; d < 128; d++) {
            float a[4], bb[4];
            *(float4*)a  = *(const float4*)(Qs + d * QK_STRIDE + r0);
            *(float4*)bb = *(const float4*)(Ks + d * QK_STRIDE + cs0);
#pragma unroll
            for (int i = 0; i < 4; i++)
#pragma unroll
                for (int j = 0; j < 4; j++)
                    s4[i][j] += a[i] * bb[j];
        }
        // causal mask (only diagonal tile needs it)
        if (k0 + FBN > q0) {
#pragma unroll
            for (int i = 0; i < 4; i++) {
                int qr = q0 + r0 + i;
#pragma unroll
                for (int j = 0; j < 4; j++)
                    if (k0 + cs0 + j > qr) s4[i][j] = -1e30f;
            }
        }
        // online softmax (rows shared across 16-lane tx groups)
        float alpha[4];
#pragma unroll
        for (int i = 0; i < 4; i++) {
            float v = fmaxf(fmaxf(s4[i][0], s4[i][1]), fmaxf(s4[i][2], s4[i][3]));
            v = fmaxf(v, __shfl_xor_sync(0xffffffffu, v, 1));
            v = fmaxf(v, __shfl_xor_sync(0xffffffffu, v, 2));
            v = fmaxf(v, __shfl_xor_sync(0xffffffffu, v, 4));
            v = fmaxf(v, __shfl_xor_sync(0xffffffffu, v, 8));
            float mnew = fmaxf(m_i[i], v);
            alpha[i] = expf(m_i[i] - mnew);
            m_i[i] = mnew;
            float sum = 0.f;
#pragma unroll
            for (int j = 0; j < 4; j++) {
                float p = expf(s4[i][j] - mnew);
                s4[i][j] = p;
                sum += p;
            }
            sum += __shfl_xor_sync(0xffffffffu, sum, 1);
            sum += __shfl_xor_sync(0xffffffffu, sum, 2);
            sum += __shfl_xor_sync(0xffffffffu, sum, 4);
            sum += __shfl_xor_sync(0xffffffffu, sum, 8);
            l_i[i] = l_i[i] * alpha[i] + sum;
        }
        // store P (row-major, float4), rescale O
#pragma unroll
        for (int i = 0; i < 4; i++)
            *(float4*)(Ps + (r0 + i) * FBN + cs0) =
                make_float4(s4[i][0], s4[i][1], s4[i][2], s4[i][3]);
#pragma unroll
        for (int i = 0; i < 4; i++)
#pragma unroll
            for (int j = 0; j < 8; j++) o[i][j] *= alpha[i];
        __syncthreads();
        // O += P @ V
#pragma unroll 2
        for (int j = 0; j < FBN; j++) {
            float p[4];
#pragma unroll
            for (int i = 0; i < 4; i++) p[i] = Ps[(r0 + i) * FBN + j];  // broadcast
            float v8[8];
            *(float4*)v8       = *(const float4*)(Vs + j * 128 + co0);
            *(float4*)(v8 + 4) = *(const float4*)(Vs + j * 128 + co0 + 4);
#pragma unroll
            for (int i = 0; i < 4; i++)
#pragma unroll
                for (int e = 0; e < 8; e++)
                    o[i][e] += p[i] * v8[e];
        }
    }
    // epilogue: comb += (1-g) * O / l
    float g = 1.f / (1.f + expf(-gate[h]));
    float w = 1.f - g;
#pragma unroll
    for (int i = 0; i < 4; i++) {
        float inv = w / l_i[i];
        float* cp = comb + ((size_t)(b * S + q0 + r0 + i)) * HID + h * HD + co0;
        float4 c0 = *(float4*)cp;
        float4 c1 = *(float4*)(cp + 4);
        c0.x += o[i][0] * inv; c0.y += o[i][1] * inv;
        c0.z += o[i][2] * inv; c0.w += o[i][3] * inv;
        c1.x += o[i][4] * inv; c1.y += o[i][5] * inv;
        c1.z += o[i][6] * inv; c1.w += o[i][7] * inv;
        *(float4*)cp       = c0;
        *(float4*)(cp + 4) = c1;
    }
}

// ---------------------------------------------------------------------------
extern "C" void kernel_launch(void* const* d_in, const int* in_sizes, int n_in,
                              void* d_out, int out_size) {
    const float* hs      = (const float*)d_in[0];
    const float* Wq      = (const float*)d_in[1];
    const float* Wk      = (const float*)d_in[2];
    const float* Wv      = (const float*)d_in[3];
    const float* Wo      = (const float*)d_in[4];
    const float* gate    = (const float*)d_in[5];
    const float* mem_in  = (const float*)d_in[6];
    const float* norm_in = (const float*)d_in[7];
    const int*   posids  = (const int*)d_in[8];
    float* out = (float*)d_out;

    const int S  = in_sizes[8];               // 2048
    const int B  = in_sizes[0] / (S * HID);   // 2
    const int BS = B * S;

    float *q, *k, *v, *comb;
    cudaGetSymbolAddress((void**)&q,    g_q);
    cudaGetSymbolAddress((void**)&k,    g_k);
    cudaGetSymbolAddress((void**)&v,    g_v);
    cudaGetSymbolAddress((void**)&comb, g_comb);

    float* out_final = out;
    float* out_mem   = out + (size_t)BS * HID;
    float* out_norm  = out_mem + (size_t)B * NKV * HD * HD;

    dim3 blk(256);

    // QKV projections (pre-RoPE)
    sgemm128<<<dim3(NH * HD / 128,  BS / 128), blk>>>(hs, Wq, q, BS, NH * HD,  HID);
    sgemm128<<<dim3(NKV * HD / 128, BS / 128), blk>>>(hs, Wk, k, BS, NKV * HD, HID);
    sgemm128<<<dim3(NKV * HD / 128, BS / 128), blk>>>(hs, Wv, v, BS, NKV * HD, HID);

    // updated_memory / updated_norm directly into d_out
    {
        int nmem = B * NKV * HD * HD, nnorm = B * NKV * HD;
        init_out_kernel<<<(nmem + 255) / 256, 256>>>(mem_in, norm_in, out_mem, out_norm,
                                                     nmem, nnorm);
    }
    mem_update_kernel<<<dim3(B * NKV, 8), blk>>>(k, v, out_mem, out_norm, B, S);

    // g * memory_output / norm -> combined buffer (pre-RoPE sigma_q)
    mem_output_kernel<<<dim3(B * NH, S / 128), blk>>>(q, mem_in, norm_in, gate, comb, B, S);

    // RoPE in place on q and k
    {
        long totq = (long)BS * NH * 64;
        rope_kernel<<<(unsigned)((totq + 255) / 256), 256>>>(q, posids, NH, S, totq);
        long totk = (long)BS * NKV * 64;
        rope_kernel<<<(unsigned)((totk + 255) / 256), 256>>>(k, posids, NKV, S, totk);
    }

    // flash attention: comb += (1-g)*attn
    {
        int smem = (128 * QK_STRIDE * 2 + FBN * 128 + FBM * FBN) * (int)sizeof(float);
        cudaFuncSetAttribute(flash_kernel, cudaFuncAttributeMaxDynamicSharedMemorySize, smem);
        flash_kernel<<<dim3(S / FBM, B * NH), blk, smem>>>(q, k, v, gate, comb, B, S);
    }

    // final projection into d_out
    sgemm128<<<dim3(HID / 128, BS / 128), blk>>>(comb, Wo, out_final, BS, HID, HID);
}

// round 11
// speedup vs baseline: 1.0010x; 1.0010x over previous
#include <cuda_runtime.h>
#include <math.h>

#define HID  2048
#define NH   16
#define NKV  8
#define HD   128
#define B_C  2
#define S_C  2048
#define BS_C (B_C * S_C)

// ---------------- scratch (device globals; no allocation allowed) ----------
__device__ float g_q[(size_t)BS_C * NH * HD];     // (B*S, 2048) pre/post-RoPE Q
__device__ float g_k[(size_t)BS_C * NKV * HD];    // (B*S, 1024)
__device__ float g_v[(size_t)BS_C * NKV * HD];    // (B*S, 1024)
__device__ float g_comb[(size_t)BS_C * HID];      // combined (B,S,2048)

__device__ __forceinline__ float elu1(float x) { return x > 0.f ? x + 1.f : expf(x); }

// ---------------- 128x128x8 SGEMM, row-major A(MxK) * B(KxN) -> C(MxN) -----
__global__ __launch_bounds__(256, 2)
void sgemm128(const float* __restrict__ A, const float* __restrict__ Bm,
              float* __restrict__ C, int M, int N, int K) {
    __shared__ float As[8][128];   // [k][m] transposed
    __shared__ float Bs[8][128];   // [k][n]
    const int tid  = threadIdx.x;
    const int tx   = tid & 15, ty = tid >> 4;
    const int row0 = blockIdx.y * 128, col0 = blockIdx.x * 128;
    const int a_row = tid >> 1,  a_col = (tid & 1) << 2;
    const int b_row = tid >> 5,  b_col = (tid & 31) << 2;
    const float* Aptr = A + (size_t)(row0 + a_row) * K + a_col;
    const float* Bptr = Bm + (size_t)b_row * N + col0 + b_col;

    float acc[8][8];
#pragma unroll
    for (int i = 0; i < 8; i++)
#pragma unroll
        for (int j = 0; j < 8; j++) acc[i][j] = 0.f;

    for (int k0 = 0; k0 < K; k0 += 8) {
        float4 av = *(const float4*)(Aptr + k0);
        As[a_col + 0][a_row] = av.x;
        As[a_col + 1][a_row] = av.y;
        As[a_col + 2][a_row] = av.z;
        As[a_col + 3][a_row] = av.w;
        *(float4*)&Bs[b_row][b_col] = *(const float4*)(Bptr + (size_t)k0 * N);
        __syncthreads();
#pragma unroll
        for (int k = 0; k < 8; k++) {
            float a[8], b[8];
            *(float4*)&a[0] = *(const float4*)&As[k][ty * 8];
            *(float4*)&a[4] = *(const float4*)&As[k][ty * 8 + 4];
            *(float4*)&b[0] = *(const float4*)&Bs[k][tx * 8];
            *(float4*)&b[4] = *(const float4*)&Bs[k][tx * 8 + 4];
#pragma unroll
            for (int i = 0; i < 8; i++)
#pragma unroll
                for (int j = 0; j < 8; j++)
                    acc[i][j] += a[i] * b[j];
        }
        __syncthreads();
    }
#pragma unroll
    for (int i = 0; i < 8; i++) {
        float* cp = C + (size_t)(row0 + ty * 8 + i) * N + col0 + tx * 8;
        *(float4*)cp       = make_float4(acc[i][0], acc[i][1], acc[i][2], acc[i][3]);
        *(float4*)(cp + 4) = make_float4(acc[i][4], acc[i][5], acc[i][6], acc[i][7]);
    }
}

// ---------------- init: copy memory_in / norm_in into output slots ---------
__global__ void init_out_kernel(const float* __restrict__ mem_in,
                                const float* __restrict__ norm_in,
                                float* __restrict__ out_mem,
                                float* __restrict__ out_norm,
                                int nmem, int nnorm) {
    int idx = blockIdx.x * blockDim.x + threadIdx.x;
    if (idx < nmem)  out_mem[idx]  = mem_in[idx];
    if (idx < nnorm) out_norm[idx] = norm_in[idx];
}

// ---------------- updated_memory += sigma_k^T @ v ; updated_norm += sum ----
// grid (B*NKV, SPLITS), block 256. Atomic-accumulate into d_out.
__global__ __launch_bounds__(256)
void mem_update_kernel(const float* __restrict__ kbuf, const float* __restrict__ vbuf,
                       float* __restrict__ out_mem, float* __restrict__ out_norm,
                       int B, int S) {
    __shared__ float As[8][128];  // sigma_k [s][d]
    __shared__ float Bs[8][128];  // v       [s][e]
    const int tid = threadIdx.x;
    const int bkv = blockIdx.x;
    const int b = bkv >> 3, kv = bkv & 7;
    const int schunk = S / gridDim.y;
    const int s0 = blockIdx.y * schunk;
    const int tx = tid & 15, ty = tid >> 4;
    const int lr = tid >> 5,  lc = (tid & 31) << 2;

    float acc[8][8];
#pragma unroll
    for (int i = 0; i < 8; i++)
#pragma unroll
        for (int j = 0; j < 8; j++) acc[i][j] = 0.f;
    float nacc = 0.f;

    for (int ks = s0; ks < s0 + schunk; ks += 8) {
        size_t rowb = (size_t)(b * S + ks + lr);
        float4 kk = *(const float4*)(kbuf + rowb * (NKV * HD) + kv * HD + lc);
        As[lr][lc + 0] = elu1(kk.x);
        As[lr][lc + 1] = elu1(kk.y);
        As[lr][lc + 2] = elu1(kk.z);
        As[lr][lc + 3] = elu1(kk.w);
        *(float4*)&Bs[lr][lc] = *(const float4*)(vbuf + rowb * (NKV * HD) + kv * HD + lc);
        __syncthreads();
        if (tid < 128) {
#pragma unroll
            for (int r = 0; r < 8; r++) nacc += As[r][tid];
        }
#pragma unroll
        for (int k = 0; k < 8; k++) {
            float a[8], bb[8];
            *(float4*)&a[0]  = *(const float4*)&As[k][ty * 8];
            *(float4*)&a[4]  = *(const float4*)&As[k][ty * 8 + 4];
            *(float4*)&bb[0] = *(const float4*)&Bs[k][tx * 8];
            *(float4*)&bb[4] = *(const float4*)&Bs[k][tx * 8 + 4];
#pragma unroll
            for (int i = 0; i < 8; i++)
#pragma unroll
                for (int j = 0; j < 8; j++)
                    acc[i][j] += a[i] * bb[j];
        }
        __syncthreads();
    }
    float* mp = out_mem + (size_t)bkv * HD * HD;
#pragma unroll
    for (int i = 0; i < 8; i++)
#pragma unroll
        for (int j = 0; j < 8; j++)
            atomicAdd(mp + (ty * 8 + i) * HD + tx * 8 + j, acc[i][j]);
    if (tid < 128) atomicAdd(out_norm + bkv * HD + tid, nacc);
}

// ---------------- memory_output = g * (sigma_q @ M) / (sigma_q . norm) -----
// grid (B*NH, S/128), block 256. Writes combined buffer (g*mem part).
__global__ __launch_bounds__(256)
void mem_output_kernel(const float* __restrict__ qbuf,
                       const float* __restrict__ mem_in,
                       const float* __restrict__ norm_in,
                       const float* __restrict__ gate,
                       float* __restrict__ comb, int B, int S) {
    __shared__ float As[8][128];  // sigma_q transposed [d][s]
    __shared__ float Bs[8][128];  // mem [d][e]
    __shared__ float Ns[8];       // norm chunk
    const int tid = threadIdx.x;
    const int bh = blockIdx.x;
    const int b = bh >> 4, h = bh & 15;
    const int kv = h & 7;                 // jnp.tile: head h -> kv = h % 8
    const int s0 = blockIdx.y * 128;
    const int tx = tid & 15, ty = tid >> 4;
    const int a_row = tid >> 1, a_col = (tid & 1) << 2;
    const int lr = tid >> 5,    lc = (tid & 31) << 2;

    const float* memp  = mem_in  + (size_t)(b * NKV + kv) * HD * HD;
    const float* normp = norm_in + (size_t)(b * NKV + kv) * HD;

    float acc[8][8];
#pragma unroll
    for (int i = 0; i < 8; i++)
#pragma unroll
        for (int j = 0; j < 8; j++) acc[i][j] = 0.f;
    float nacc[8] = {0.f, 0.f, 0.f, 0.f, 0.f, 0.f, 0.f, 0.f};

    for (int d0 = 0; d0 < HD; d0 += 8) {
        float4 qv = *(const float4*)(qbuf + ((size_t)(b * S + s0 + a_row)) * (NH * HD)
                                     + h * HD + d0 + a_col);
        As[a_col + 0][a_row] = elu1(qv.x);
        As[a_col + 1][a_row] = elu1(qv.y);
        As[a_col + 2][a_row] = elu1(qv.z);
        As[a_col + 3][a_row] = elu1(qv.w);
        *(float4*)&Bs[lr][lc] = *(const float4*)(memp + (d0 + lr) * HD + lc);
        if (tid < 8) Ns[tid] = normp[d0 + tid];
        __syncthreads();
#pragma unroll
        for (int k = 0; k < 8; k++) {
            float a[8], bb[8];
            *(float4*)&a[0]  = *(const float4*)&As[k][ty * 8];
            *(float4*)&a[4]  = *(const float4*)&As[k][ty * 8 + 4];
            *(float4*)&bb[0] = *(const float4*)&Bs[k][tx * 8];
            *(float4*)&bb[4] = *(const float4*)&Bs[k][tx * 8 + 4];
            float nk = Ns[k];
#pragma unroll
            for (int i = 0; i < 8; i++) {
                nacc[i] += a[i] * nk;
#pragma unroll
                for (int j = 0; j < 8; j++)
                    acc[i][j] += a[i] * bb[j];
            }
        }
        __syncthreads();
    }
    float g = 1.f / (1.f + expf(-gate[h]));
#pragma unroll
    for (int i = 0; i < 8; i++) {
        float gi = g / nacc[i];
        float* cp = comb + ((size_t)(b * S + s0 + ty * 8 + i)) * HID + h * HD + tx * 8;
        *(float4*)cp       = make_float4(acc[i][0]*gi, acc[i][1]*gi, acc[i][2]*gi, acc[i][3]*gi);
        *(float4*)(cp + 4) = make_float4(acc[i][4]*gi, acc[i][5]*gi, acc[i][6]*gi, acc[i][7]*gi);
    }
}

// ---------------- RoPE in place -------------------------------------------
__global__ void rope_kernel(float* __restrict__ buf, const int* __restrict__ posids,
                            int heads, int S, long total) {
    long idx = (long)blockIdx.x * blockDim.x + threadIdx.x;
    if (idx >= total) return;
    int dh = (int)(idx & 63);
    long t = idx >> 6;
    int h = (int)(t % heads);
    long bs = t / heads;
    int s = (int)(bs % S);
    float pos = (float)posids[s];
    float inv = powf(10000.f, -((float)(2 * dh)) * (1.f / 128.f));
    float ang = pos * inv;
    float sn, c;
    sincosf(ang, &sn, &c);
    float* p = buf + bs * (size_t)heads * HD + (size_t)h * HD;
    float x1 = p[dh], x2 = p[dh + 64];
    p[dh]      = x1 * c - x2 * sn;
    p[dh + 64] = x2 * c + x1 * sn;
}

// ---------------- causal flash attention, adds (1-g)*attn into comb --------
// grid (S/64, B*NH), block 256, dynamic smem.
#define FBM 64
#define FBN 64
#define QK_STRIDE 68   // padded d-major stride (16B-aligned, kills conflicts)

__global__ void flash_kernel(const float* __restrict__ qbuf,
                             const float* __restrict__ kbuf,
                             const float* __restrict__ vbuf,
                             const float* __restrict__ gate,
                             float* __restrict__ comb, int B, int S) {
    extern __shared__ float sm[];
    float* Qs = sm;                          // [128][QK_STRIDE] d-major
    float* Ks = Qs + 128 * QK_STRIDE;        // [128][QK_STRIDE] d-major
    float* Vs = Ks + 128 * QK_STRIDE;        // [64][128] row-major
    float* Ps = Vs + FBN * 128;              // [64][64] row-major

    const int tid = threadIdx.x;
    const int bh = blockIdx.y;
    const int b = bh >> 4, h = bh & 15;
    const int kvh = h >> 1;                  // jnp.repeat: head h -> kv = h / 2
    const int qt = (gridDim.x - 1) - blockIdx.x;   // heavy tiles launch first
    const int q0 = qt * FBM;
    const float scale = 0.08838834764831845f;      // 1/sqrt(128)

    // load Q tile (scaled), transpose to d-major
    {
        const float* qp = qbuf + ((size_t)(b * S + q0)) * (NH * HD) + h * HD;
        for (int t = tid; t < FBM * 32; t += 256) {
            int r = t >> 5; int c4 = (t & 31) << 2;
            float4 v = *(const float4*)(qp + (size_t)r * (NH * HD) + c4);
            Qs[(c4 + 0) * QK_STRIDE + r] = v.x * scale;
            Qs[(c4 + 1) * QK_STRIDE + r] = v.y * scale;
            Qs[(c4 + 2) * QK_STRIDE + r] = v.z * scale;
            Qs[(c4 + 3) * QK_STRIDE + r] = v.w * scale;
        }
    }
    const int tx = tid & 15, ty = tid >> 4;
    const int r0 = ty * 4;       // rows (score & O)
    const int cs0 = tx * 4;      // score cols
    const int co0 = tx * 8;      // O cols

    float o[4][8];
#pragma unroll
    for (int i = 0; i < 4; i++)
#pragma unroll
        for (int j = 0; j < 8; j++) o[i][j] = 0.f;
    float m_i[4] = {-1e30f, -1e30f, -1e30f, -1e30f};
    float l_i[4] = {0.f, 0.f, 0.f, 0.f};

    const int nkt = qt + 1;
    for (int kt = 0; kt < nkt; kt++) {
        const int k0 = kt * FBN;
        __syncthreads();   // protect K/V/P reuse (and Qs on first iter)
        const float* kp = kbuf + ((size_t)(b * S + k0)) * (NKV * HD) + kvh * HD;
        const float* vp = vbuf + ((size_t)(b * S + k0)) * (NKV * HD) + kvh * HD;
        for (int t = tid; t < FBN * 32; t += 256) {
            int r = t >> 5; int c4 = (t & 31) << 2;
            float4 kk = *(const float4*)(kp + (size_t)r * (NKV * HD) + c4);
            Ks[(c4 + 0) * QK_STRIDE + r] = kk.x;
            Ks[(c4 + 1) * QK_STRIDE + r] = kk.y;
            Ks[(c4 + 2) * QK_STRIDE + r] = kk.z;
            Ks[(c4 + 3) * QK_STRIDE + r] = kk.w;
            *(float4*)(Vs + r * 128 + c4) = *(const float4*)(vp + (size_t)r * (NKV * HD) + c4);
        }
        __syncthreads();

        // scores: S[64][64] = Q K^T (scaled)
        float s4[4][4];
#pragma unroll
        for (int i = 0; i < 4; i++)
#pragma unroll
            for (int j = 0; j < 4; j++) s4[i][j] = 0.f;
#pragma unroll 4
        for (int d = 0; d < 128; d++) {
            float a[4], bb[4];
            *(float4*)a  = *(const float4*)(Qs + d * QK_STRIDE + r0);
            *(float4*)bb = *(const float4*)(Ks + d * QK_STRIDE + cs0);
#pragma unroll
            for (int i = 0; i < 4; i++)
#pragma unroll
                for (int j = 0; j < 4; j++)
                    s4[i][j] += a[i] * bb[j];
        }
        // causal mask (only diagonal tile needs it)
        if (k0 + FBN > q0) {
#pragma unroll
            for (int i = 0; i < 4; i++) {
                int qr = q0 + r0 + i;
#pragma unroll
                for (int j = 0; j < 4; j++)
                    if (k0 + cs0 + j > qr) s4[i][j] = -1e30f;
            }
        }
        // online softmax (rows shared across 16-lane tx groups)
        float alpha[4];
#pragma unroll
        for (int i = 0; i < 4; i++) {
            float v = fmaxf(fmaxf(s4[i][0], s4[i][1]), fmaxf(s4[i][2], s4[i][3]));
            v = fmaxf(v, __shfl_xor_sync(0xffffffffu, v, 1));
            v = fmaxf(v, __shfl_xor_sync(0xffffffffu, v, 2));
            v = fmaxf(v, __shfl_xor_sync(0xffffffffu, v, 4));
            v = fmaxf(v, __shfl_xor_sync(0xffffffffu, v, 8));
            float mnew = fmaxf(m_i[i], v);
            alpha[i] = expf(m_i[i] - mnew);
            m_i[i] = mnew;
            float sum = 0.f;
#pragma unroll
            for (int j = 0; j < 4; j++) {
                float p = expf(s4[i][j] - mnew);
                s4[i][j] = p;
                sum += p;
            }
            sum += __shfl_xor_sync(0xffffffffu, sum, 1);
            sum += __shfl_xor_sync(0xffffffffu, sum, 2);
            sum += __shfl_xor_sync(0xffffffffu, sum, 4);
            sum += __shfl_xor_sync(0xffffffffu, sum, 8);
            l_i[i] = l_i[i] * alpha[i] + sum;
        }
        // store P (row-major, float4), rescale O
#pragma unroll
        for (int i = 0; i < 4; i++)
            *(float4*)(Ps + (r0 + i) * FBN + cs0) =
                make_float4(s4[i][0], s4[i][1], s4[i][2], s4[i][3]);
#pragma unroll
        for (int i = 0; i < 4; i++)
#pragma unroll
            for (int j = 0; j < 8; j++) o[i][j] *= alpha[i];
        __syncthreads();
        // O += P @ V
#pragma unroll 2
        for (int j = 0; j < FBN; j++) {
            float p[4];
#pragma unroll
            for (int i = 0; i < 4; i++) p[i] = Ps[(r0 + i) * FBN + j];  // broadcast
            float v8[8];
            *(float4*)v8       = *(const float4*)(Vs + j * 128 + co0);
            *(float4*)(v8 + 4) = *(const float4*)(Vs + j * 128 + co0 + 4);
#pragma unroll
            for (int i = 0; i < 4; i++)
#pragma unroll
                for (int e = 0; e < 8; e++)
                    o[i][e] += p[i] * v8[e];
        }
    }
    // epilogue: comb += (1-g) * O / l
    float g = 1.f / (1.f + expf(-gate[h]));
    float w = 1.f - g;
#pragma unroll
    for (int i = 0; i < 4; i++) {
        float inv = w / l_i[i];
        float* cp = comb + ((size_t)(b * S + q0 + r0 + i)) * HID + h * HD + co0;
        float4 c0 = *(float4*)cp;
        float4 c1 = *(float4*)(cp + 4);
        c0.x += o[i][0] * inv; c0.y += o[i][1] * inv;
        c0.z += o[i][2] * inv; c0.w += o[i][3] * inv;
        c1.x += o[i][4] * inv; c1.y += o[i][5] * inv;
        c1.z += o[i][6] * inv; c1.w += o[i][7] * inv;
        *(float4*)cp       = c0;
        *(float4*)(cp + 4) = c1;
    }
}

// ---------------------------------------------------------------------------
extern "C" void kernel_launch(void* const* d_in, const int* in_sizes, int n_in,
                              void* d_out, int out_size) {
    const float* hs      = (const float*)d_in[0];
    const float* Wq      = (const float*)d_in[1];
    const float* Wk      = (const float*)d_in[2];
    const float* Wv      = (const float*)d_in[3];
    const float* Wo      = (const float*)d_in[4];
    const float* gate    = (const float*)d_in[5];
    const float* mem_in  = (const float*)d_in[6];
    const float* norm_in = (const float*)d_in[7];
    const int*   posids  = (const int*)d_in[8];
    float* out = (float*)d_out;

    const int S  = in_sizes[8];               // 2048
    const int B  = in_sizes[0] / (S * HID);   // 2
    const int BS = B * S;

    float *q, *k, *v, *comb;
    cudaGetSymbolAddress((void**)&q,    g_q);
    cudaGetSymbolAddress((void**)&k,    g_k);
    cudaGetSymbolAddress((void**)&v,    g_v);
    cudaGetSymbolAddress((void**)&comb, g_comb);

    float* out_final = out;
    float* out_mem   = out + (size_t)BS * HID;
    float* out_norm  = out_mem + (size_t)B * NKV * HD * HD;

    dim3 blk(256);

    // QKV projections (pre-RoPE)
    sgemm128<<<dim3(NH * HD / 128,  BS / 128), blk>>>(hs, Wq, q, BS, NH * HD,  HID);
    sgemm128<<<dim3(NKV * HD / 128, BS / 128), blk>>>(hs, Wk, k, BS, NKV * HD, HID);
    sgemm128<<<dim3(NKV * HD / 128, BS / 128), blk>>>(hs, Wv, v, BS, NKV * HD, HID);

    // updated_memory / updated_norm directly into d_out
    {
        int nmem = B * NKV * HD * HD, nnorm = B * NKV * HD;
        init_out_kernel<<<(nmem + 255) / 256, 256>>>(mem_in, norm_in, out_mem, out_norm,
                                                     nmem, nnorm);
    }
    mem_update_kernel<<<dim3(B * NKV, 8), blk>>>(k, v, out_mem, out_norm, B, S);

    // g * memory_output / norm -> combined buffer (pre-RoPE sigma_q)
    mem_output_kernel<<<dim3(B * NH, S / 128), blk>>>(q, mem_in, norm_in, gate, comb, B, S);

    // RoPE in place on q and k
    {
        long totq = (long)BS * NH * 64;
        rope_kernel<<<(unsigned)((totq + 255) / 256), 256>>>(q, posids, NH, S, totq);
        long totk = (long)BS * NKV * 64;
        rope_kernel<<<(unsigned)((totk + 255) / 256), 256>>>(k, posids, NKV, S, totk);
    }

    // flash attention: comb += (1-g)*attn
    {
        int smem = (128 * QK_STRIDE * 2 + FBN * 128 + FBM * FBN) * (int)sizeof(float);
        cudaFuncSetAttribute(flash_kernel, cudaFuncAttributeMaxDynamicSharedMemorySize, smem);
        flash_kernel<<<dim3(S / FBM, B * NH), blk, smem>>>(q, k, v, gate, comb, B, S);
    }

    // final projection into d_out
    sgemm128<<<dim3(HID / 128, BS / 128), blk>>>(comb, Wo, out_final, BS, HID, HID);
}

// round 12
// speedup vs baseline: 1.2577x; 1.2564x over previous
#include <cuda_runtime.h>
#include <math.h>
#include <stdint.h>

#define HID  2048
#define NH   16
#define NKV  8
#define HD   128
#define B_C  2
#define S_C  2048
#define BS_C (B_C * S_C)

// ---------------- scratch (device globals; no allocation allowed) ----------
__device__ float g_q[(size_t)BS_C * NH * HD];     // (B*S, 2048) pre/post-RoPE Q
__device__ float g_k[(size_t)BS_C * NKV * HD];    // (B*S, 1024)
__device__ float g_v[(size_t)BS_C * NKV * HD];    // (B*S, 1024)
__device__ float g_comb[(size_t)BS_C * HID];      // combined (B,S,2048)

__device__ __forceinline__ float elu1(float x) { return x > 0.f ? x + 1.f : expf(x); }

// ===========================================================================
// TF32 split-precision GEMM: C[M,N] = A[M,K] @ B[K,N], all row-major fp32.
// 128x128 block tile, K-chunk 32, 8 warps (2x4), warp tile 64x32.
// Each fp32 operand is split x = hi + lo (hi = top 19 bits, tf32-exact);
// D += Ah*Bh + Ah*Bl + Al*Bh  -> ~2^-22 relative error (fp32-grade).
// ===========================================================================
#define ASTR 36    // A smem row stride (bank = 4*m + k  -> conflict-free frags)
#define BSTR 136   // B smem row stride (bank = 8*k + n  -> conflict-free frags)

__device__ __forceinline__ void mma_tf32(float* d, const uint32_t* a, const uint32_t* b) {
    asm volatile(
        "mma.sync.aligned.m16n8k8.row.col.f32.tf32.tf32.f32 "
        "{%0,%1,%2,%3}, {%4,%5,%6,%7}, {%8,%9}, {%0,%1,%2,%3};\n"
        : "+f"(d[0]), "+f"(d[1]), "+f"(d[2]), "+f"(d[3])
        : "r"(a[0]), "r"(a[1]), "r"(a[2]), "r"(a[3]), "r"(b[0]), "r"(b[1]));
}

__device__ __forceinline__ void split4(float4 v, float4& hi, float4& lo) {
    hi.x = __uint_as_float(__float_as_uint(v.x) & 0xffffe000u); lo.x = v.x - hi.x;
    hi.y = __uint_as_float(__float_as_uint(v.y) & 0xffffe000u); lo.y = v.y - hi.y;
    hi.z = __uint_as_float(__float_as_uint(v.z) & 0xffffe000u); lo.z = v.z - hi.z;
    hi.w = __uint_as_float(__float_as_uint(v.w) & 0xffffe000u); lo.w = v.w - hi.w;
}

__global__ __launch_bounds__(256)
void gemm_tf32(const float* __restrict__ A, const float* __restrict__ Bm,
               float* __restrict__ C, int M, int N, int K) {
    extern __shared__ float sm[];
    float* Ah = sm;                    // [128][ASTR]
    float* Al = Ah + 128 * ASTR;
    float* Bh = Al + 128 * ASTR;       // [32][BSTR]
    float* Bl = Bh + 32 * BSTR;

    const int tid  = threadIdx.x;
    const int wid  = tid >> 5, lane = tid & 31;
    const int wm   = wid >> 2, wn = wid & 3;
    const int mbase = wm * 64, nbase = wn * 32;
    const int lr = lane >> 2, lk = lane & 3;
    const int row0 = blockIdx.y * 128, col0 = blockIdx.x * 128;

    // per-thread global load coordinates (4 float4 each for A and B tiles)
    int am[4], ak[4], br[4], bn[4];
#pragma unroll
    for (int it = 0; it < 4; it++) {
        int l = tid + 256 * it;
        am[it] = l >> 3;         ak[it] = (l & 7) << 2;   // A: 128 rows x 32 cols
        br[it] = l >> 5;         bn[it] = (l & 31) << 2;  // B: 32 rows x 128 cols
    }

    float acc[4][4][4];
#pragma unroll
    for (int i = 0; i < 4; i++)
#pragma unroll
        for (int j = 0; j < 4; j++)
#pragma unroll
            for (int r = 0; r < 4; r++) acc[i][j][r] = 0.f;

    const int nchunk = K >> 5;
    float4 ra[4], rb[4];
    // prefetch chunk 0
#pragma unroll
    for (int it = 0; it < 4; it++) {
        ra[it] = *(const float4*)(A  + (size_t)(row0 + am[it]) * K + ak[it]);
        rb[it] = *(const float4*)(Bm + (size_t)br[it] * N + col0 + bn[it]);
    }

    for (int c = 0; c < nchunk; c++) {
        // split + store current chunk to smem
#pragma unroll
        for (int it = 0; it < 4; it++) {
            float4 hi, lo;
            split4(ra[it], hi, lo);
            *(float4*)(Ah + am[it] * ASTR + ak[it]) = hi;
            *(float4*)(Al + am[it] * ASTR + ak[it]) = lo;
            split4(rb[it], hi, lo);
            *(float4*)(Bh + br[it] * BSTR + bn[it]) = hi;
            *(float4*)(Bl + br[it] * BSTR + bn[it]) = lo;
        }
        __syncthreads();

        // prefetch next chunk (latency overlapped with the MMAs below)
        if (c + 1 < nchunk) {
            int k0 = (c + 1) << 5;
#pragma unroll
            for (int it = 0; it < 4; it++) {
                ra[it] = *(const float4*)(A  + (size_t)(row0 + am[it]) * K + k0 + ak[it]);
                rb[it] = *(const float4*)(Bm + (size_t)(k0 + br[it]) * N + col0 + bn[it]);
            }
        }

#pragma unroll
        for (int ks = 0; ks < 4; ks++) {
            const int kb = ks * 8;
            uint32_t afh[4][4], afl[4][4], bfh[4][2], bfl[4][2];
#pragma unroll
            for (int mf = 0; mf < 4; mf++) {
                const float* p  = Ah + (mbase + mf * 16 + lr) * ASTR + kb + lk;
                const float* pl = Al + (mbase + mf * 16 + lr) * ASTR + kb + lk;
                afh[mf][0] = __float_as_uint(p[0]);
                afh[mf][1] = __float_as_uint(p[8 * ASTR]);
                afh[mf][2] = __float_as_uint(p[4]);
                afh[mf][3] = __float_as_uint(p[8 * ASTR + 4]);
                afl[mf][0] = __float_as_uint(pl[0]);
                afl[mf][1] = __float_as_uint(pl[8 * ASTR]);
                afl[mf][2] = __float_as_uint(pl[4]);
                afl[mf][3] = __float_as_uint(pl[8 * ASTR + 4]);
            }
#pragma unroll
            for (int nf = 0; nf < 4; nf++) {
                const float* p  = Bh + (kb + lk) * BSTR + nbase + nf * 8 + lr;
                const float* pl = Bl + (kb + lk) * BSTR + nbase + nf * 8 + lr;
                bfh[nf][0] = __float_as_uint(p[0]);
                bfh[nf][1] = __float_as_uint(p[4 * BSTR]);
                bfl[nf][0] = __float_as_uint(pl[0]);
                bfl[nf][1] = __float_as_uint(pl[4 * BSTR]);
            }
#pragma unroll
            for (int mf = 0; mf < 4; mf++)
#pragma unroll
                for (int nf = 0; nf < 4; nf++) {
                    mma_tf32(acc[mf][nf], afh[mf], bfh[nf]);
                    mma_tf32(acc[mf][nf], afh[mf], bfl[nf]);
                    mma_tf32(acc[mf][nf], afl[mf], bfh[nf]);
                }
        }
        __syncthreads();
    }

    // epilogue: c0/c1 at (row, 2*lk .. +1), c2/c3 at (row+8, ...)
#pragma unroll
    for (int mf = 0; mf < 4; mf++) {
        int r = row0 + mbase + mf * 16 + lr;
#pragma unroll
        for (int nf = 0; nf < 4; nf++) {
            int cidx = col0 + nbase + nf * 8 + 2 * lk;
            *(float2*)(C + (size_t)r * N + cidx)       = make_float2(acc[mf][nf][0], acc[mf][nf][1]);
            *(float2*)(C + (size_t)(r + 8) * N + cidx) = make_float2(acc[mf][nf][2], acc[mf][nf][3]);
        }
    }
}
#define GEMM_SMEM ((128 * ASTR * 2 + 32 * BSTR * 2) * (int)sizeof(float))

// ---------------- init: copy memory_in / norm_in into output slots ---------
__global__ void init_out_kernel(const float* __restrict__ mem_in,
                                const float* __restrict__ norm_in,
                                float* __restrict__ out_mem,
                                float* __restrict__ out_norm,
                                int nmem, int nnorm) {
    int idx = blockIdx.x * blockDim.x + threadIdx.x;
    if (idx < nmem)  out_mem[idx]  = mem_in[idx];
    if (idx < nnorm) out_norm[idx] = norm_in[idx];
}

// ---------------- updated_memory += sigma_k^T @ v ; updated_norm += sum ----
__global__ __launch_bounds__(256)
void mem_update_kernel(const float* __restrict__ kbuf, const float* __restrict__ vbuf,
                       float* __restrict__ out_mem, float* __restrict__ out_norm,
                       int B, int S) {
    __shared__ float As[8][128];  // sigma_k [s][d]
    __shared__ float Bs[8][128];  // v       [s][e]
    const int tid = threadIdx.x;
    const int bkv = blockIdx.x;
    const int b = bkv >> 3, kv = bkv & 7;
    const int schunk = S / gridDim.y;
    const int s0 = blockIdx.y * schunk;
    const int tx = tid & 15, ty = tid >> 4;
    const int lr = tid >> 5,  lc = (tid & 31) << 2;

    float acc[8][8];
#pragma unroll
    for (int i = 0; i < 8; i++)
#pragma unroll
        for (int j = 0; j < 8; j++) acc[i][j] = 0.f;
    float nacc = 0.f;

    for (int ks = s0; ks < s0 + schunk; ks += 8) {
        size_t rowb = (size_t)(b * S + ks + lr);
        float4 kk = *(const float4*)(kbuf + rowb * (NKV * HD) + kv * HD + lc);
        As[lr][lc + 0] = elu1(kk.x);
        As[lr][lc + 1] = elu1(kk.y);
        As[lr][lc + 2] = elu1(kk.z);
        As[lr][lc + 3] = elu1(kk.w);
        *(float4*)&Bs[lr][lc] = *(const float4*)(vbuf + rowb * (NKV * HD) + kv * HD + lc);
        __syncthreads();
        if (tid < 128) {
#pragma unroll
            for (int r = 0; r < 8; r++) nacc += As[r][tid];
        }
#pragma unroll
        for (int k = 0; k < 8; k++) {
            float a[8], bb[8];
            *(float4*)&a[0]  = *(const float4*)&As[k][ty * 8];
            *(float4*)&a[4]  = *(const float4*)&As[k][ty * 8 + 4];
            *(float4*)&bb[0] = *(const float4*)&Bs[k][tx * 8];
            *(float4*)&bb[4] = *(const float4*)&Bs[k][tx * 8 + 4];
#pragma unroll
            for (int i = 0; i < 8; i++)
#pragma unroll
                for (int j = 0; j < 8; j++)
                    acc[i][j] += a[i] * bb[j];
        }
        __syncthreads();
    }
    float* mp = out_mem + (size_t)bkv * HD * HD;
#pragma unroll
    for (int i = 0; i < 8; i++)
#pragma unroll
        for (int j = 0; j < 8; j++)
            atomicAdd(mp + (ty * 8 + i) * HD + tx * 8 + j, acc[i][j]);
    if (tid < 128) atomicAdd(out_norm + bkv * HD + tid, nacc);
}

// ---------------- memory_output = g * (sigma_q @ M) / (sigma_q . norm) -----
__global__ __launch_bounds__(256)
void mem_output_kernel(const float* __restrict__ qbuf,
                       const float* __restrict__ mem_in,
                       const float* __restrict__ norm_in,
                       const float* __restrict__ gate,
                       float* __restrict__ comb, int B, int S) {
    __shared__ float As[8][128];  // sigma_q transposed [d][s]
    __shared__ float Bs[8][128];  // mem [d][e]
    __shared__ float Ns[8];       // norm chunk
    const int tid = threadIdx.x;
    const int bh = blockIdx.x;
    const int b = bh >> 4, h = bh & 15;
    const int kv = h & 7;                 // jnp.tile: head h -> kv = h % 8
    const int s0 = blockIdx.y * 128;
    const int tx = tid & 15, ty = tid >> 4;
    const int a_row = tid >> 1, a_col = (tid & 1) << 2;
    const int lr = tid >> 5,    lc = (tid & 31) << 2;

    const float* memp  = mem_in  + (size_t)(b * NKV + kv) * HD * HD;
    const float* normp = norm_in + (size_t)(b * NKV + kv) * HD;

    float acc[8][8];
#pragma unroll
    for (int i = 0; i < 8; i++)
#pragma unroll
        for (int j = 0; j < 8; j++) acc[i][j] = 0.f;
    float nacc[8] = {0.f, 0.f, 0.f, 0.f, 0.f, 0.f, 0.f, 0.f};

    for (int d0 = 0; d0 < HD; d0 += 8) {
        float4 qv = *(const float4*)(qbuf + ((size_t)(b * S + s0 + a_row)) * (NH * HD)
                                     + h * HD + d0 + a_col);
        As[a_col + 0][a_row] = elu1(qv.x);
        As[a_col + 1][a_row] = elu1(qv.y);
        As[a_col + 2][a_row] = elu1(qv.z);
        As[a_col + 3][a_row] = elu1(qv.w);
        *(float4*)&Bs[lr][lc] = *(const float4*)(memp + (d0 + lr) * HD + lc);
        if (tid < 8) Ns[tid] = normp[d0 + tid];
        __syncthreads();
#pragma unroll
        for (int k = 0; k < 8; k++) {
            float a[8], bb[8];
            *(float4*)&a[0]  = *(const float4*)&As[k][ty * 8];
            *(float4*)&a[4]  = *(const float4*)&As[k][ty * 8 + 4];
            *(float4*)&bb[0] = *(const float4*)&Bs[k][tx * 8];
            *(float4*)&bb[4] = *(const float4*)&Bs[k][tx * 8 + 4];
            float nk = Ns[k];
#pragma unroll
            for (int i = 0; i < 8; i++) {
                nacc[i] += a[i] * nk;
#pragma unroll
                for (int j = 0; j < 8; j++)
                    acc[i][j] += a[i] * bb[j];
            }
        }
        __syncthreads();
    }
    float g = 1.f / (1.f + expf(-gate[h]));
#pragma unroll
    for (int i = 0; i < 8; i++) {
        float gi = g / nacc[i];
        float* cp = comb + ((size_t)(b * S + s0 + ty * 8 + i)) * HID + h * HD + tx * 8;
        *(float4*)cp       = make_float4(acc[i][0]*gi, acc[i][1]*gi, acc[i][2]*gi, acc[i][3]*gi);
        *(float4*)(cp + 4) = make_float4(acc[i][4]*gi, acc[i][5]*gi, acc[i][6]*gi, acc[i][7]*gi);
    }
}

// ---------------- RoPE in place -------------------------------------------
__global__ void rope_kernel(float* __restrict__ buf, const int* __restrict__ posids,
                            int heads, int S, long total) {
    long idx = (long)blockIdx.x * blockDim.x + threadIdx.x;
    if (idx >= total) return;
    int dh = (int)(idx & 63);
    long t = idx >> 6;
    int h = (int)(t % heads);
    long bs = t / heads;
    int s = (int)(bs % S);
    float pos = (float)posids[s];
    float inv = powf(10000.f, -((float)(2 * dh)) * (1.f / 128.f));
    float ang = pos * inv;
    float sn, c;
    sincosf(ang, &sn, &c);
    float* p = buf + bs * (size_t)heads * HD + (size_t)h * HD;
    float x1 = p[dh], x2 = p[dh + 64];
    p[dh]      = x1 * c - x2 * sn;
    p[dh + 64] = x2 * c + x1 * sn;
}

// ---------------- causal flash attention, adds (1-g)*attn into comb --------
#define FBM 64
#define FBN 64
#define QK_STRIDE 68

__global__ void flash_kernel(const float* __restrict__ qbuf,
                             const float* __restrict__ kbuf,
                             const float* __restrict__ vbuf,
                             const float* __restrict__ gate,
                             float* __restrict__ comb, int B, int S) {
    extern __shared__ float smf[];
    float* Qs = smf;                         // [128][QK_STRIDE] d-major
    float* Ks = Qs + 128 * QK_STRIDE;        // [128][QK_STRIDE] d-major
    float* Vs = Ks + 128 * QK_STRIDE;        // [64][128] row-major
    float* Ps = Vs + FBN * 128;              // [64][64] row-major

    const int tid = threadIdx.x;
    const int bh = blockIdx.y;
    const int b = bh >> 4, h = bh & 15;
    const int kvh = h >> 1;                  // jnp.repeat: head h -> kv = h / 2
    const int qt = (gridDim.x - 1) - blockIdx.x;
    const int q0 = qt * FBM;
    const float scale = 0.08838834764831845f;

    {
        const float* qp = qbuf + ((size_t)(b * S + q0)) * (NH * HD) + h * HD;
        for (int t = tid; t < FBM * 32; t += 256) {
            int r = t >> 5; int c4 = (t & 31) << 2;
            float4 v = *(const float4*)(qp + (size_t)r * (NH * HD) + c4);
            Qs[(c4 + 0) * QK_STRIDE + r] = v.x * scale;
            Qs[(c4 + 1) * QK_STRIDE + r] = v.y * scale;
            Qs[(c4 + 2) * QK_STRIDE + r] = v.z * scale;
            Qs[(c4 + 3) * QK_STRIDE + r] = v.w * scale;
        }
    }
    const int tx = tid & 15, ty = tid >> 4;
    const int r0 = ty * 4;
    const int cs0 = tx * 4;
    const int co0 = tx * 8;

    float o[4][8];
#pragma unroll
    for (int i = 0; i < 4; i++)
#pragma unroll
        for (int j = 0; j < 8; j++) o[i][j] = 0.f;
    float m_i[4] = {-1e30f, -1e30f, -1e30f, -1e30f};
    float l_i[4] = {0.f, 0.f, 0.f, 0.f};

    const int nkt = qt + 1;
    for (int kt = 0; kt < nkt; kt++) {
        const int k0 = kt * FBN;
        __syncthreads();
        const float* kp = kbuf + ((size_t)(b * S + k0)) * (NKV * HD) + kvh * HD;
        const float* vp = vbuf + ((size_t)(b * S + k0)) * (NKV * HD) + kvh * HD;
        for (int t = tid; t < FBN * 32; t += 256) {
            int r = t >> 5; int c4 = (t & 31) << 2;
            float4 kk = *(const float4*)(kp + (size_t)r * (NKV * HD) + c4);
            Ks[(c4 + 0) * QK_STRIDE + r] = kk.x;
            Ks[(c4 + 1) * QK_STRIDE + r] = kk.y;
            Ks[(c4 + 2) * QK_STRIDE + r] = kk.z;
            Ks[(c4 + 3) * QK_STRIDE + r] = kk.w;
            *(float4*)(Vs + r * 128 + c4) = *(const float4*)(vp + (size_t)r * (NKV * HD) + c4);
        }
        __syncthreads();

        float s4[4][4];
#pragma unroll
        for (int i = 0; i < 4; i++)
#pragma unroll
            for (int j = 0; j < 4; j++) s4[i][j] = 0.f;
#pragma unroll 4
        for (int d = 0; d < 128; d++) {
            float a[4], bb[4];
            *(float4*)a  = *(const float4*)(Qs + d * QK_STRIDE + r0);
            *(float4*)bb = *(const float4*)(Ks + d * QK_STRIDE + cs0);
#pragma unroll
            for (int i = 0; i < 4; i++)
#pragma unroll
                for (int j = 0; j < 4; j++)
                    s4[i][j] += a[i] * bb[j];
        }
        if (k0 + FBN > q0) {
#pragma unroll
            for (int i = 0; i < 4; i++) {
                int qr = q0 + r0 + i;
#pragma unroll
                for (int j = 0; j < 4; j++)
                    if (k0 + cs0 + j > qr) s4[i][j] = -1e30f;
            }
        }
        float alpha[4];
#pragma unroll
        for (int i = 0; i < 4; i++) {
            float v = fmaxf(fmaxf(s4[i][0], s4[i][1]), fmaxf(s4[i][2], s4[i][3]));
            v = fmaxf(v, __shfl_xor_sync(0xffffffffu, v, 1));
            v = fmaxf(v, __shfl_xor_sync(0xffffffffu, v, 2));
            v = fmaxf(v, __shfl_xor_sync(0xffffffffu, v, 4));
            v = fmaxf(v, __shfl_xor_sync(0xffffffffu, v, 8));
            float mnew = fmaxf(m_i[i], v);
            alpha[i] = expf(m_i[i] - mnew);
            m_i[i] = mnew;
            float sum = 0.f;
#pragma unroll
            for (int j = 0; j < 4; j++) {
                float p = expf(s4[i][j] - mnew);
                s4[i][j] = p;
                sum += p;
            }
            sum += __shfl_xor_sync(0xffffffffu, sum, 1);
            sum += __shfl_xor_sync(0xffffffffu, sum, 2);
            sum += __shfl_xor_sync(0xffffffffu, sum, 4);
            sum += __shfl_xor_sync(0xffffffffu, sum, 8);
            l_i[i] = l_i[i] * alpha[i] + sum;
        }
#pragma unroll
        for (int i = 0; i < 4; i++)
            *(float4*)(Ps + (r0 + i) * FBN + cs0) =
                make_float4(s4[i][0], s4[i][1], s4[i][2], s4[i][3]);
#pragma unroll
        for (int i = 0; i < 4; i++)
#pragma unroll
            for (int j = 0; j < 8; j++) o[i][j] *= alpha[i];
        __syncthreads();
#pragma unroll 2
        for (int j = 0; j < FBN; j++) {
            float p[4];
#pragma unroll
            for (int i = 0; i < 4; i++) p[i] = Ps[(r0 + i) * FBN + j];
            float v8[8];
            *(float4*)v8       = *(const float4*)(Vs + j * 128 + co0);
            *(float4*)(v8 + 4) = *(const float4*)(Vs + j * 128 + co0 + 4);
#pragma unroll
            for (int i = 0; i < 4; i++)
#pragma unroll
                for (int e = 0; e < 8; e++)
                    o[i][e] += p[i] * v8[e];
        }
    }
    float g = 1.f / (1.f + expf(-gate[h]));
    float w = 1.f - g;
#pragma unroll
    for (int i = 0; i < 4; i++) {
        float inv = w / l_i[i];
        float* cp = comb + ((size_t)(b * S + q0 + r0 + i)) * HID + h * HD + co0;
        float4 c0 = *(float4*)cp;
        float4 c1 = *(float4*)(cp + 4);
        c0.x += o[i][0] * inv; c0.y += o[i][1] * inv;
        c0.z += o[i][2] * inv; c0.w += o[i][3] * inv;
        c1.x += o[i][4] * inv; c1.y += o[i][5] * inv;
        c1.z += o[i][6] * inv; c1.w += o[i][7] * inv;
        *(float4*)cp       = c0;
        *(float4*)(cp + 4) = c1;
    }
}

// ---------------------------------------------------------------------------
extern "C" void kernel_launch(void* const* d_in, const int* in_sizes, int n_in,
                              void* d_out, int out_size) {
    const float* hs      = (const float*)d_in[0];
    const float* Wq      = (const float*)d_in[1];
    const float* Wk      = (const float*)d_in[2];
    const float* Wv      = (const float*)d_in[3];
    const float* Wo      = (const float*)d_in[4];
    const float* gate    = (const float*)d_in[5];
    const float* mem_in  = (const float*)d_in[6];
    const float* norm_in = (const float*)d_in[7];
    const int*   posids  = (const int*)d_in[8];
    float* out = (float*)d_out;

    const int S  = in_sizes[8];               // 2048
    const int B  = in_sizes[0] / (S * HID);   // 2
    const int BS = B * S;

    float *q, *k, *v, *comb;
    cudaGetSymbolAddress((void**)&q,    g_q);
    cudaGetSymbolAddress((void**)&k,    g_k);
    cudaGetSymbolAddress((void**)&v,    g_v);
    cudaGetSymbolAddress((void**)&comb, g_comb);

    float* out_final = out;
    float* out_mem   = out + (size_t)BS * HID;
    float* out_norm  = out_mem + (size_t)B * NKV * HD * HD;

    dim3 blk(256);
    cudaFuncSetAttribute(gemm_tf32, cudaFuncAttributeMaxDynamicSharedMemorySize, GEMM_SMEM);

    // QKV projections (pre-RoPE) on tensor cores (tf32 split)
    gemm_tf32<<<dim3(NH * HD / 128,  BS / 128), blk, GEMM_SMEM>>>(hs, Wq, q, BS, NH * HD,  HID);
    gemm_tf32<<<dim3(NKV * HD / 128, BS / 128), blk, GEMM_SMEM>>>(hs, Wk, k, BS, NKV * HD, HID);
    gemm_tf32<<<dim3(NKV * HD / 128, BS / 128), blk, GEMM_SMEM>>>(hs, Wv, v, BS, NKV * HD, HID);

    // updated_memory / updated_norm directly into d_out
    {
        int nmem = B * NKV * HD * HD, nnorm = B * NKV * HD;
        init_out_kernel<<<(nmem + 255) / 256, 256>>>(mem_in, norm_in, out_mem, out_norm,
                                                     nmem, nnorm);
    }
    mem_update_kernel<<<dim3(B * NKV, 8), blk>>>(k, v, out_mem, out_norm, B, S);

    // g * memory_output / norm -> combined buffer (pre-RoPE sigma_q)
    mem_output_kernel<<<dim3(B * NH, S / 128), blk>>>(q, mem_in, norm_in, gate, comb, B, S);

    // RoPE in place on q and k
    {
        long totq = (long)BS * NH * 64;
        rope_kernel<<<(unsigned)((totq + 255) / 256), 256>>>(q, posids, NH, S, totq);
        long totk = (long)BS * NKV * 64;
        rope_kernel<<<(unsigned)((totk + 255) / 256), 256>>>(k, posids, NKV, S, totk);
    }

    // flash attention: comb += (1-g)*attn
    {
        int smem = (128 * QK_STRIDE * 2 + FBN * 128 + FBM * FBN) * (int)sizeof(float);
        cudaFuncSetAttribute(flash_kernel, cudaFuncAttributeMaxDynamicSharedMemorySize, smem);
        flash_kernel<<<dim3(S / FBM, B * NH), blk, smem>>>(q, k, v, gate, comb, B, S);
    }

    // final projection into d_out (tensor cores)
    gemm_tf32<<<dim3(HID / 128, BS / 128), blk, GEMM_SMEM>>>(comb, Wo, out_final, BS, HID, HID);
}

// round 13
// speedup vs baseline: 1.2581x; 1.0003x over previous
#include <cuda_runtime.h>
#include <math.h>
#include <stdint.h>

#define HID  2048
#define NH   16
#define NKV  8
#define HD   128
#define B_C  2
#define S_C  2048
#define BS_C (B_C * S_C)

// ---------------- scratch (device globals; no allocation allowed) ----------
__device__ float g_q[(size_t)BS_C * NH * HD];     // (B*S, 2048) pre/post-RoPE Q
__device__ float g_k[(size_t)BS_C * NKV * HD];    // (B*S, 1024)
__device__ float g_v[(size_t)BS_C * NKV * HD];    // (B*S, 1024)
__device__ float g_comb[(size_t)BS_C * HID];      // combined (B,S,2048)

__device__ __forceinline__ float elu1(float x) { return x > 0.f ? x + 1.f : expf(x); }

// ===========================================================================
// TF32 split-precision GEMM: C[M,N] = A[M,K] @ B[K,N], all row-major fp32.
// 128x128 block tile, K-chunk 32, 8 warps (2x4), warp tile 64x32.
// Each fp32 operand is split x = hi + lo (hi = top 19 bits, tf32-exact);
// D += Ah*Bh + Ah*Bl + Al*Bh  -> ~2^-22 relative error (fp32-grade).
// ===========================================================================
#define ASTR 36    // A smem row stride (bank = 4*m + k  -> conflict-free frags)
#define BSTR 136   // B smem row stride (bank = 8*k + n  -> conflict-free frags)

__device__ __forceinline__ void mma_tf32(float* d, const uint32_t* a, const uint32_t* b) {
    asm volatile(
        "mma.sync.aligned.m16n8k8.row.col.f32.tf32.tf32.f32 "
        "{%0,%1,%2,%3}, {%4,%5,%6,%7}, {%8,%9}, {%0,%1,%2,%3};\n"
        : "+f"(d[0]), "+f"(d[1]), "+f"(d[2]), "+f"(d[3])
        : "r"(a[0]), "r"(a[1]), "r"(a[2]), "r"(a[3]), "r"(b[0]), "r"(b[1]));
}

__device__ __forceinline__ void split4(float4 v, float4& hi, float4& lo) {
    hi.x = __uint_as_float(__float_as_uint(v.x) & 0xffffe000u); lo.x = v.x - hi.x;
    hi.y = __uint_as_float(__float_as_uint(v.y) & 0xffffe000u); lo.y = v.y - hi.y;
    hi.z = __uint_as_float(__float_as_uint(v.z) & 0xffffe000u); lo.z = v.z - hi.z;
    hi.w = __uint_as_float(__float_as_uint(v.w) & 0xffffe000u); lo.w = v.w - hi.w;
}

__global__ __launch_bounds__(256)
void gemm_tf32(const float* __restrict__ A, const float* __restrict__ Bm,
               float* __restrict__ C, int M, int N, int K) {
    extern __shared__ float sm[];
    float* Ah = sm;                    // [128][ASTR]
    float* Al = Ah + 128 * ASTR;
    float* Bh = Al + 128 * ASTR;       // [32][BSTR]
    float* Bl = Bh + 32 * BSTR;

    const int tid  = threadIdx.x;
    const int wid  = tid >> 5, lane = tid & 31;
    const int wm   = wid >> 2, wn = wid & 3;
    const int mbase = wm * 64, nbase = wn * 32;
    const int lr = lane >> 2, lk = lane & 3;
    const int row0 = blockIdx.y * 128, col0 = blockIdx.x * 128;

    // per-thread global load coordinates (4 float4 each for A and B tiles)
    int am[4], ak[4], br[4], bn[4];
#pragma unroll
    for (int it = 0; it < 4; it++) {
        int l = tid + 256 * it;
        am[it] = l >> 3;         ak[it] = (l & 7) << 2;   // A: 128 rows x 32 cols
        br[it] = l >> 5;         bn[it] = (l & 31) << 2;  // B: 32 rows x 128 cols
    }

    float acc[4][4][4];
#pragma unroll
    for (int i = 0; i < 4; i++)
#pragma unroll
        for (int j = 0; j < 4; j++)
#pragma unroll
            for (int r = 0; r < 4; r++) acc[i][j][r] = 0.f;

    const int nchunk = K >> 5;
    float4 ra[4], rb[4];
    // prefetch chunk 0
#pragma unroll
    for (int it = 0; it < 4; it++) {
        ra[it] = *(const float4*)(A  + (size_t)(row0 + am[it]) * K + ak[it]);
        rb[it] = *(const float4*)(Bm + (size_t)br[it] * N + col0 + bn[it]);
    }

    for (int c = 0; c < nchunk; c++) {
        // split + store current chunk to smem
#pragma unroll
        for (int it = 0; it < 4; it++) {
            float4 hi, lo;
            split4(ra[it], hi, lo);
            *(float4*)(Ah + am[it] * ASTR + ak[it]) = hi;
            *(float4*)(Al + am[it] * ASTR + ak[it]) = lo;
            split4(rb[it], hi, lo);
            *(float4*)(Bh + br[it] * BSTR + bn[it]) = hi;
            *(float4*)(Bl + br[it] * BSTR + bn[it]) = lo;
        }
        __syncthreads();

        // prefetch next chunk (latency overlapped with the MMAs below)
        if (c + 1 < nchunk) {
            int k0 = (c + 1) << 5;
#pragma unroll
            for (int it = 0; it < 4; it++) {
                ra[it] = *(const float4*)(A  + (size_t)(row0 + am[it]) * K + k0 + ak[it]);
                rb[it] = *(const float4*)(Bm + (size_t)(k0 + br[it]) * N + col0 + bn[it]);
            }
        }

#pragma unroll
        for (int ks = 0; ks < 4; ks++) {
            const int kb = ks * 8;
            uint32_t afh[4][4], afl[4][4], bfh[4][2], bfl[4][2];
#pragma unroll
            for (int mf = 0; mf < 4; mf++) {
                const float* p  = Ah + (mbase + mf * 16 + lr) * ASTR + kb + lk;
                const float* pl = Al + (mbase + mf * 16 + lr) * ASTR + kb + lk;
                afh[mf][0] = __float_as_uint(p[0]);
                afh[mf][1] = __float_as_uint(p[8 * ASTR]);
                afh[mf][2] = __float_as_uint(p[4]);
                afh[mf][3] = __float_as_uint(p[8 * ASTR + 4]);
                afl[mf][0] = __float_as_uint(pl[0]);
                afl[mf][1] = __float_as_uint(pl[8 * ASTR]);
                afl[mf][2] = __float_as_uint(pl[4]);
                afl[mf][3] = __float_as_uint(pl[8 * ASTR + 4]);
            }
#pragma unroll
            for (int nf = 0; nf < 4; nf++) {
                const float* p  = Bh + (kb + lk) * BSTR + nbase + nf * 8 + lr;
                const float* pl = Bl + (kb + lk) * BSTR + nbase + nf * 8 + lr;
                bfh[nf][0] = __float_as_uint(p[0]);
                bfh[nf][1] = __float_as_uint(p[4 * BSTR]);
                bfl[nf][0] = __float_as_uint(pl[0]);
                bfl[nf][1] = __float_as_uint(pl[4 * BSTR]);
            }
#pragma unroll
            for (int mf = 0; mf < 4; mf++)
#pragma unroll
                for (int nf = 0; nf < 4; nf++) {
                    mma_tf32(acc[mf][nf], afh[mf], bfh[nf]);
                    mma_tf32(acc[mf][nf], afh[mf], bfl[nf]);
                    mma_tf32(acc[mf][nf], afl[mf], bfh[nf]);
                }
        }
        __syncthreads();
    }

    // epilogue: c0/c1 at (row, 2*lk .. +1), c2/c3 at (row+8, ...)
#pragma unroll
    for (int mf = 0; mf < 4; mf++) {
        int r = row0 + mbase + mf * 16 + lr;
#pragma unroll
        for (int nf = 0; nf < 4; nf++) {
            int cidx = col0 + nbase + nf * 8 + 2 * lk;
            *(float2*)(C + (size_t)r * N + cidx)       = make_float2(acc[mf][nf][0], acc[mf][nf][1]);
            *(float2*)(C + (size_t)(r + 8) * N + cidx) = make_float2(acc[mf][nf][2], acc[mf][nf][3]);
        }
    }
}
#define GEMM_SMEM ((128 * ASTR * 2 + 32 * BSTR * 2) * (int)sizeof(float))

// ---------------- init: copy memory_in / norm_in into output slots ---------
__global__ void init_out_kernel(const float* __restrict__ mem_in,
                                const float* __restrict__ norm_in,
                                float* __restrict__ out_mem,
                                float* __restrict__ out_norm,
                                int nmem, int nnorm) {
    int idx = blockIdx.x * blockDim.x + threadIdx.x;
    if (idx < nmem)  out_mem[idx]  = mem_in[idx];
    if (idx < nnorm) out_norm[idx] = norm_in[idx];
}

// ---------------- updated_memory += sigma_k^T @ v ; updated_norm += sum ----
__global__ __launch_bounds__(256)
void mem_update_kernel(const float* __restrict__ kbuf, const float* __restrict__ vbuf,
                       float* __restrict__ out_mem, float* __restrict__ out_norm,
                       int B, int S) {
    __shared__ float As[8][128];  // sigma_k [s][d]
    __shared__ float Bs[8][128];  // v       [s][e]
    const int tid = threadIdx.x;
    const int bkv = blockIdx.x;
    const int b = bkv >> 3, kv = bkv & 7;
    const int schunk = S / gridDim.y;
    const int s0 = blockIdx.y * schunk;
    const int tx = tid & 15, ty = tid >> 4;
    const int lr = tid >> 5,  lc = (tid & 31) << 2;

    float acc[8][8];
#pragma unroll
    for (int i = 0; i < 8; i++)
#pragma unroll
        for (int j = 0; j < 8; j++) acc[i][j] = 0.f;
    float nacc = 0.f;

    for (int ks = s0; ks < s0 + schunk; ks += 8) {
        size_t rowb = (size_t)(b * S + ks + lr);
        float4 kk = *(const float4*)(kbuf + rowb * (NKV * HD) + kv * HD + lc);
        As[lr][lc + 0] = elu1(kk.x);
        As[lr][lc + 1] = elu1(kk.y);
        As[lr][lc + 2] = elu1(kk.z);
        As[lr][lc + 3] = elu1(kk.w);
        *(float4*)&Bs[lr][lc] = *(const float4*)(vbuf + rowb * (NKV * HD) + kv * HD + lc);
        __syncthreads();
        if (tid < 128) {
#pragma unroll
            for (int r = 0; r < 8; r++) nacc += As[r][tid];
        }
#pragma unroll
        for (int k = 0; k < 8; k++) {
            float a[8], bb[8];
            *(float4*)&a[0]  = *(const float4*)&As[k][ty * 8];
            *(float4*)&a[4]  = *(const float4*)&As[k][ty * 8 + 4];
            *(float4*)&bb[0] = *(const float4*)&Bs[k][tx * 8];
            *(float4*)&bb[4] = *(const float4*)&Bs[k][tx * 8 + 4];
#pragma unroll
            for (int i = 0; i < 8; i++)
#pragma unroll
                for (int j = 0; j < 8; j++)
                    acc[i][j] += a[i] * bb[j];
        }
        __syncthreads();
    }
    float* mp = out_mem + (size_t)bkv * HD * HD;
#pragma unroll
    for (int i = 0; i < 8; i++)
#pragma unroll
        for (int j = 0; j < 8; j++)
            atomicAdd(mp + (ty * 8 + i) * HD + tx * 8 + j, acc[i][j]);
    if (tid < 128) atomicAdd(out_norm + bkv * HD + tid, nacc);
}

// ---------------- memory_output = g * (sigma_q @ M) / (sigma_q . norm) -----
__global__ __launch_bounds__(256)
void mem_output_kernel(const float* __restrict__ qbuf,
                       const float* __restrict__ mem_in,
                       const float* __restrict__ norm_in,
                       const float* __restrict__ gate,
                       float* __restrict__ comb, int B, int S) {
    __shared__ float As[8][128];  // sigma_q transposed [d][s]
    __shared__ float Bs[8][128];  // mem [d][e]
    __shared__ float Ns[8];       // norm chunk
    const int tid = threadIdx.x;
    const int bh = blockIdx.x;
    const int b = bh >> 4, h = bh & 15;
    const int kv = h & 7;                 // jnp.tile: head h -> kv = h % 8
    const int s0 = blockIdx.y * 128;
    const int tx = tid & 15, ty = tid >> 4;
    const int a_row = tid >> 1, a_col = (tid & 1) << 2;
    const int lr = tid >> 5,    lc = (tid & 31) << 2;

    const float* memp  = mem_in  + (size_t)(b * NKV + kv) * HD * HD;
    const float* normp = norm_in + (size_t)(b * NKV + kv) * HD;

    float acc[8][8];
#pragma unroll
    for (int i = 0; i < 8; i++)
#pragma unroll
        for (int j = 0; j < 8; j++) acc[i][j] = 0.f;
    float nacc[8] = {0.f, 0.f, 0.f, 0.f, 0.f, 0.f, 0.f, 0.f};

    for (int d0 = 0; d0 < HD; d0 += 8) {
        float4 qv = *(const float4*)(qbuf + ((size_t)(b * S + s0 + a_row)) * (NH * HD)
                                     + h * HD + d0 + a_col);
        As[a_col + 0][a_row] = elu1(qv.x);
        As[a_col + 1][a_row] = elu1(qv.y);
        As[a_col + 2][a_row] = elu1(qv.z);
        As[a_col + 3][a_row] = elu1(qv.w);
        *(float4*)&Bs[lr][lc] = *(const float4*)(memp + (d0 + lr) * HD + lc);
        if (tid < 8) Ns[tid] = normp[d0 + tid];
        __syncthreads();
#pragma unroll
        for (int k = 0; k < 8; k++) {
            float a[8], bb[8];
            *(float4*)&a[0]  = *(const float4*)&As[k][ty * 8];
            *(float4*)&a[4]  = *(const float4*)&As[k][ty * 8 + 4];
            *(float4*)&bb[0] = *(const float4*)&Bs[k][tx * 8];
            *(float4*)&bb[4] = *(const float4*)&Bs[k][tx * 8 + 4];
            float nk = Ns[k];
#pragma unroll
            for (int i = 0; i < 8; i++) {
                nacc[i] += a[i] * nk;
#pragma unroll
                for (int j = 0; j < 8; j++)
                    acc[i][j] += a[i] * bb[j];
            }
        }
        __syncthreads();
    }
    float g = 1.f / (1.f + expf(-gate[h]));
#pragma unroll
    for (int i = 0; i < 8; i++) {
        float gi = g / nacc[i];
        float* cp = comb + ((size_t)(b * S + s0 + ty * 8 + i)) * HID + h * HD + tx * 8;
        *(float4*)cp       = make_float4(acc[i][0]*gi, acc[i][1]*gi, acc[i][2]*gi, acc[i][3]*gi);
        *(float4*)(cp + 4) = make_float4(acc[i][4]*gi, acc[i][5]*gi, acc[i][6]*gi, acc[i][7]*gi);
    }
}

// ---------------- RoPE in place -------------------------------------------
__global__ void rope_kernel(float* __restrict__ buf, const int* __restrict__ posids,
                            int heads, int S, long total) {
    long idx = (long)blockIdx.x * blockDim.x + threadIdx.x;
    if (idx >= total) return;
    int dh = (int)(idx & 63);
    long t = idx >> 6;
    int h = (int)(t % heads);
    long bs = t / heads;
    int s = (int)(bs % S);
    float pos = (float)posids[s];
    float inv = powf(10000.f, -((float)(2 * dh)) * (1.f / 128.f));
    float ang = pos * inv;
    float sn, c;
    sincosf(ang, &sn, &c);
    float* p = buf + bs * (size_t)heads * HD + (size_t)h * HD;
    float x1 = p[dh], x2 = p[dh + 64];
    p[dh]      = x1 * c - x2 * sn;
    p[dh + 64] = x2 * c + x1 * sn;
}

// ---------------- causal flash attention, adds (1-g)*attn into comb --------
#define FBM 64
#define FBN 64
#define QK_STRIDE 68

__global__ void flash_kernel(const float* __restrict__ qbuf,
                             const float* __restrict__ kbuf,
                             const float* __restrict__ vbuf,
                             const float* __restrict__ gate,
                             float* __restrict__ comb, int B, int S) {
    extern __shared__ float smf[];
    float* Qs = smf;                         // [128][QK_STRIDE] d-major
    float* Ks = Qs + 128 * QK_STRIDE;        // [128][QK_STRIDE] d-major
    float* Vs = Ks + 128 * QK_STRIDE;        // [64][128] row-major
    float* Ps = Vs + FBN * 128;              // [64][64] row-major

    const int tid = threadIdx.x;
    const int bh = blockIdx.y;
    const int b = bh >> 4, h = bh & 15;
    const int kvh = h >> 1;                  // jnp.repeat: head h -> kv = h / 2
    const int qt = (gridDim.x - 1) - blockIdx.x;
    const int q0 = qt * FBM;
    const float scale = 0.08838834764831845f;

    {
        const float* qp = qbuf + ((size_t)(b * S + q0)) * (NH * HD) + h * HD;
        for (int t = tid; t < FBM * 32; t += 256) {
            int r = t >> 5; int c4 = (t & 31) << 2;
            float4 v = *(const float4*)(qp + (size_t)r * (NH * HD) + c4);
            Qs[(c4 + 0) * QK_STRIDE + r] = v.x * scale;
            Qs[(c4 + 1) * QK_STRIDE + r] = v.y * scale;
            Qs[(c4 + 2) * QK_STRIDE + r] = v.z * scale;
            Qs[(c4 + 3) * QK_STRIDE + r] = v.w * scale;
        }
    }
    const int tx = tid & 15, ty = tid >> 4;
    const int r0 = ty * 4;
    const int cs0 = tx * 4;
    const int co0 = tx * 8;

    float o[4][8];
#pragma unroll
    for (int i = 0; i < 4; i++)
#pragma unroll
        for (int j = 0; j < 8; j++) o[i][j] = 0.f;
    float m_i[4] = {-1e30f, -1e30f, -1e30f, -1e30f};
    float l_i[4] = {0.f, 0.f, 0.f, 0.f};

    const int nkt = qt + 1;
    for (int kt = 0; kt < nkt; kt++) {
        const int k0 = kt * FBN;
        __syncthreads();
        const float* kp = kbuf + ((size_t)(b * S + k0)) * (NKV * HD) + kvh * HD;
        const float* vp = vbuf + ((size_t)(b * S + k0)) * (NKV * HD) + kvh * HD;
        for (int t = tid; t < FBN * 32; t += 256) {
            int r = t >> 5; int c4 = (t & 31) << 2;
            float4 kk = *(const float4*)(kp + (size_t)r * (NKV * HD) + c4);
            Ks[(c4 + 0) * QK_STRIDE + r] = kk.x;
            Ks[(c4 + 1) * QK_STRIDE + r] = kk.y;
            Ks[(c4 + 2) * QK_STRIDE + r] = kk.z;
            Ks[(c4 + 3) * QK_STRIDE + r] = kk.w;
            *(float4*)(Vs + r * 128 + c4) = *(const float4*)(vp + (size_t)r * (NKV * HD) + c4);
        }
        __syncthreads();

        float s4[4][4];
#pragma unroll
        for (int i = 0; i < 4; i++)
#pragma unroll
            for (int j = 0; j < 4; j++) s4[i][j] = 0.f;
#pragma unroll 4
        for (int d = 0; d < 128; d++) {
            float a[4], bb[4];
            *(float4*)a  = *(const float4*)(Qs + d * QK_STRIDE + r0);
            *(float4*)bb = *(const float4*)(Ks + d * QK_STRIDE + cs0);
#pragma unroll
            for (int i = 0; i < 4; i++)
#pragma unroll
                for (int j = 0; j < 4; j++)
                    s4[i][j] += a[i] * bb[j];
        }
        if (k0 + FBN > q0) {
#pragma unroll
            for (int i = 0; i < 4; i++) {
                int qr = q0 + r0 + i;
#pragma unroll
                for (int j = 0; j < 4; j++)
                    if (k0 + cs0 + j > qr) s4[i][j] = -1e30f;
            }
        }
        float alpha[4];
#pragma unroll
        for (int i = 0; i < 4; i++) {
            float v = fmaxf(fmaxf(s4[i][0], s4[i][1]), fmaxf(s4[i][2], s4[i][3]));
            v = fmaxf(v, __shfl_xor_sync(0xffffffffu, v, 1));
            v = fmaxf(v, __shfl_xor_sync(0xffffffffu, v, 2));
            v = fmaxf(v, __shfl_xor_sync(0xffffffffu, v, 4));
            v = fmaxf(v, __shfl_xor_sync(0xffffffffu, v, 8));
            float mnew = fmaxf(m_i[i], v);
            alpha[i] = expf(m_i[i] - mnew);
            m_i[i] = mnew;
            float sum = 0.f;
#pragma unroll
            for (int j = 0; j < 4; j++) {
                float p = expf(s4[i][j] - mnew);
                s4[i][j] = p;
                sum += p;
            }
            sum += __shfl_xor_sync(0xffffffffu, sum, 1);
            sum += __shfl_xor_sync(0xffffffffu, sum, 2);
            sum += __shfl_xor_sync(0xffffffffu, sum, 4);
            sum += __shfl_xor_sync(0xffffffffu, sum, 8);
            l_i[i] = l_i[i] * alpha[i] + sum;
        }
#pragma unroll
        for (int i = 0; i < 4; i++)
            *(float4*)(Ps + (r0 + i) * FBN + cs0) =
                make_float4(s4[i][0], s4[i][1], s4[i][2], s4[i][3]);
#pragma unroll
        for (int i = 0; i < 4; i++)
#pragma unroll
            for (int j = 0; j < 8; j++) o[i][j] *= alpha[i];
        __syncthreads();
#pragma unroll 2
        for (int j = 0; j < FBN; j++) {
            float p[4];
#pragma unroll
            for (int i = 0; i < 4; i++) p[i] = Ps[(r0 + i) * FBN + j];
            float v8[8];
            *(float4*)v8       = *(const float4*)(Vs + j * 128 + co0);
            *(float4*)(v8 + 4) = *(const float4*)(Vs + j * 128 + co0 + 4);
#pragma unroll
            for (int i = 0; i < 4; i++)
#pragma unroll
                for (int e = 0; e < 8; e++)
                    o[i][e] += p[i] * v8[e];
        }
    }
    float g = 1.f / (1.f + expf(-gate[h]));
    float w = 1.f - g;
#pragma unroll
    for (int i = 0; i < 4; i++) {
        float inv = w / l_i[i];
        float* cp = comb + ((size_t)(b * S + q0 + r0 + i)) * HID + h * HD + co0;
        float4 c0 = *(float4*)cp;
        float4 c1 = *(float4*)(cp + 4);
        c0.x += o[i][0] * inv; c0.y += o[i][1] * inv;
        c0.z += o[i][2] * inv; c0.w += o[i][3] * inv;
        c1.x += o[i][4] * inv; c1.y += o[i][5] * inv;
        c1.z += o[i][6] * inv; c1.w += o[i][7] * inv;
        *(float4*)cp       = c0;
        *(float4*)(cp + 4) = c1;
    }
}

// ---------------------------------------------------------------------------
extern "C" void kernel_launch(void* const* d_in, const int* in_sizes, int n_in,
                              void* d_out, int out_size) {
    const float* hs      = (const float*)d_in[0];
    const float* Wq      = (const float*)d_in[1];
    const float* Wk      = (const float*)d_in[2];
    const float* Wv      = (const float*)d_in[3];
    const float* Wo      = (const float*)d_in[4];
    const float* gate    = (const float*)d_in[5];
    const float* mem_in  = (const float*)d_in[6];
    const float* norm_in = (const float*)d_in[7];
    const int*   posids  = (const int*)d_in[8];
    float* out = (float*)d_out;

    const int S  = in_sizes[8];               // 2048
    const int B  = in_sizes[0] / (S * HID);   // 2
    const int BS = B * S;

    float *q, *k, *v, *comb;
    cudaGetSymbolAddress((void**)&q,    g_q);
    cudaGetSymbolAddress((void**)&k,    g_k);
    cudaGetSymbolAddress((void**)&v,    g_v);
    cudaGetSymbolAddress((void**)&comb, g_comb);

    float* out_final = out;
    float* out_mem   = out + (size_t)BS * HID;
    float* out_norm  = out_mem + (size_t)B * NKV * HD * HD;

    dim3 blk(256);
    cudaFuncSetAttribute(gemm_tf32, cudaFuncAttributeMaxDynamicSharedMemorySize, GEMM_SMEM);

    // QKV projections (pre-RoPE) on tensor cores (tf32 split)
    gemm_tf32<<<dim3(NH * HD / 128,  BS / 128), blk, GEMM_SMEM>>>(hs, Wq, q, BS, NH * HD,  HID);
    gemm_tf32<<<dim3(NKV * HD / 128, BS / 128), blk, GEMM_SMEM>>>(hs, Wk, k, BS, NKV * HD, HID);
    gemm_tf32<<<dim3(NKV * HD / 128, BS / 128), blk, GEMM_SMEM>>>(hs, Wv, v, BS, NKV * HD, HID);

    // updated_memory / updated_norm directly into d_out
    {
        int nmem = B * NKV * HD * HD, nnorm = B * NKV * HD;
        init_out_kernel<<<(nmem + 255) / 256, 256>>>(mem_in, norm_in, out_mem, out_norm,
                                                     nmem, nnorm);
    }
    mem_update_kernel<<<dim3(B * NKV, 8), blk>>>(k, v, out_mem, out_norm, B, S);

    // g * memory_output / norm -> combined buffer (pre-RoPE sigma_q)
    mem_output_kernel<<<dim3(B * NH, S / 128), blk>>>(q, mem_in, norm_in, gate, comb, B, S);

    // RoPE in place on q and k
    {
        long totq = (long)BS * NH * 64;
        rope_kernel<<<(unsigned)((totq + 255) / 256), 256>>>(q, posids, NH, S, totq);
        long totk = (long)BS * NKV * 64;
        rope_kernel<<<(unsigned)((totk + 255) / 256), 256>>>(k, posids, NKV, S, totk);
    }

    // flash attention: comb += (1-g)*attn
    {
        int smem = (128 * QK_STRIDE * 2 + FBN * 128 + FBM * FBN) * (int)sizeof(float);
        cudaFuncSetAttribute(flash_kernel, cudaFuncAttributeMaxDynamicSharedMemorySize, smem);
        flash_kernel<<<dim3(S / FBM, B * NH), blk, smem>>>(q, k, v, gate, comb, B, S);
    }

    // final projection into d_out (tensor cores)
    gemm_tf32<<<dim3(HID / 128, BS / 128), blk, GEMM_SMEM>>>(comb, Wo, out_final, BS, HID, HID);
}